// round 11
// baseline (speedup 1.0000x reference)
#include <cuda_runtime.h>
#include <cuda_fp16.h>
#include <cstdint>
#include <cstddef>

// Problem constants
#define N_NODES 50000
#define N_PAD   50048
#define KNBR    32
#define FDIM    128
#define EDIM    8
#define KDIM    1024          // FDIM * EDIM

// G as fp16, rows [i][kk], kk = n*128 + l
// (__device__ globals zero-init; padded rows [50000,50048) stay zero.)
__device__ __half g_h[(size_t)N_PAD * KDIM];   // 102.5 MB
// W rearranged to [kk][m] fp16
__device__ __half wt_h[KDIM * FDIM];
// fp16 copy of nodes (halves the 819 MB gather to 410 MB)
__device__ __half nodes_h[(size_t)N_NODES * FDIM];   // 12.8 MB

// ---------------------------------------------------------------------------
// helpers
// ---------------------------------------------------------------------------
__device__ __forceinline__ uint32_t smem_u32(const void* p) {
    uint32_t a;
    asm("{ .reg .u64 t; cvta.to.shared.u64 t, %1; cvt.u32.u64 %0, t; }" : "=r"(a) : "l"(p));
    return a;
}

__device__ __forceinline__ void cp_async16(uint32_t dst, const void* src) {
    asm volatile("cp.async.cg.shared.global [%0], [%1], 16;" :: "r"(dst), "l"(src));
}
__device__ __forceinline__ void cp_commit() {
    asm volatile("cp.async.commit_group;");
}

__device__ __forceinline__ void ldm_x4(uint32_t* r, uint32_t addr) {
    asm volatile("ldmatrix.sync.aligned.m8n8.x4.shared.b16 {%0,%1,%2,%3}, [%4];"
                 : "=r"(r[0]), "=r"(r[1]), "=r"(r[2]), "=r"(r[3]) : "r"(addr));
}
__device__ __forceinline__ void ldm_x4t(uint32_t* r, uint32_t addr) {
    asm volatile("ldmatrix.sync.aligned.m8n8.x4.trans.shared.b16 {%0,%1,%2,%3}, [%4];"
                 : "=r"(r[0]), "=r"(r[1]), "=r"(r[2]), "=r"(r[3]) : "r"(addr));
}

__device__ __forceinline__ void mma_f16(float* c, const uint32_t* a, const uint32_t* b) {
    asm volatile(
        "mma.sync.aligned.m16n8k16.row.col.f32.f16.f16.f32 "
        "{%0,%1,%2,%3}, {%4,%5,%6,%7}, {%8,%9}, {%0,%1,%2,%3};"
        : "+f"(c[0]), "+f"(c[1]), "+f"(c[2]), "+f"(c[3])
        : "r"(a[0]), "r"(a[1]), "r"(a[2]), "r"(a[3]), "r"(b[0]), "r"(b[1]));
}

__device__ __forceinline__ void fma4(float4& a, float s, const float4& x) {
    a.x = fmaf(s, x.x, a.x);
    a.y = fmaf(s, x.y, a.y);
    a.z = fmaf(s, x.z, a.z);
    a.w = fmaf(s, x.w, a.w);
}

// ---------------------------------------------------------------------------
// Kernel 0a: w (F,F,E) -> wt_h [kk][m],  kk = n*128 + l
// ---------------------------------------------------------------------------
__global__ void transpose_w_kernel(const float* __restrict__ w) {
    int idx = blockIdx.x * blockDim.x + threadIdx.x;
    if (idx >= KDIM * FDIM) return;
    int kk = idx >> 7;          // n*128 + l
    int m  = idx & 127;
    int n  = kk >> 7;
    int l  = kk & 127;
    wt_h[idx] = __float2half_rn(w[(l * FDIM + m) * EDIM + n]);
}

// ---------------------------------------------------------------------------
// Kernel 0b: nodes fp32 -> fp16 table (halves gather bytes in stage 1)
// ---------------------------------------------------------------------------
__global__ void convert_nodes_kernel(const float* __restrict__ nodes) {
    int idx = blockIdx.x * blockDim.x + threadIdx.x;   // processes 4 elements
    if (idx * 4 >= N_NODES * FDIM) return;
    const float4 v = *(const float4*)(nodes + idx * 4);
    __half2 a = __floats2half2_rn(v.x, v.y);
    __half2 b = __floats2half2_rn(v.z, v.w);
    *(uint2*)&nodes_h[(size_t)idx * 4] = make_uint2(*(uint32_t*)&a, *(uint32_t*)&b);
}

// ---------------------------------------------------------------------------
// Kernel 1: stage 1 — G row; fp16 gather, fp32 accumulate, fp16 store
// One warp per node i. Lane owns l = lane*4..lane*4+3.
// nlist is int32 (proven on hardware).
// ---------------------------------------------------------------------------
__global__ void __launch_bounds__(256) stage1_kernel(
    const int* __restrict__ nlist,
    const float* __restrict__ edges)
{
    __shared__ int   s_nb[8][KNBR];
    __shared__ float s_e[8][KNBR * EDIM];

    const int warp = threadIdx.x >> 5;
    const int lane = threadIdx.x & 31;
    const int i = blockIdx.x * 8 + warp;

    int nbi = nlist[(size_t)i * KNBR + lane];
    nbi = nbi < 0 ? 0 : (nbi >= N_NODES ? N_NODES - 1 : nbi);   // safety clamp
    s_nb[warp][lane] = nbi;

    const float4* e4 = (const float4*)(edges + (size_t)i * (KNBR * EDIM));
    float4* se4 = (float4*)s_e[warp];
    se4[lane * 2 + 0] = e4[lane * 2 + 0];
    se4[lane * 2 + 1] = e4[lane * 2 + 1];
    __syncwarp();

    float4 acc[EDIM];
#pragma unroll
    for (int n = 0; n < EDIM; n++) acc[n] = make_float4(0.f, 0.f, 0.f, 0.f);

#pragma unroll 4
    for (int j = 0; j < KNBR; j++) {
        const int nb = s_nb[warp][j];
        // fp16 gather: 8 bytes per lane (4 halves), convert to fp32
        const uint2 xr = *(const uint2*)(nodes_h + (size_t)nb * FDIM + lane * 4);
        const float2 f01 = __half22float2(*(const __half2*)&xr.x);
        const float2 f23 = __half22float2(*(const __half2*)&xr.y);
        const float4 x = make_float4(f01.x, f01.y, f23.x, f23.y);
        const float4 e0 = *(const float4*)&s_e[warp][j * 8 + 0];
        const float4 e1 = *(const float4*)&s_e[warp][j * 8 + 4];
        fma4(acc[0], e0.x, x);
        fma4(acc[1], e0.y, x);
        fma4(acc[2], e0.z, x);
        fma4(acc[3], e0.w, x);
        fma4(acc[4], e1.x, x);
        fma4(acc[5], e1.y, x);
        fma4(acc[6], e1.z, x);
        fma4(acc[7], e1.w, x);
    }

    const size_t rbase = (size_t)i * KDIM + lane * 4;
#pragma unroll
    for (int n = 0; n < EDIM; n++) {
        __half2 a = __floats2half2_rn(acc[n].x, acc[n].y);
        __half2 b = __floats2half2_rn(acc[n].z, acc[n].w);
        *(uint2*)&g_h[rbase + n * FDIM] = make_uint2(*(uint32_t*)&a, *(uint32_t*)&b);
    }
}

// ---------------------------------------------------------------------------
// Kernel 2: mma.sync fp16 single-product GEMM, BM=64 x BN=128, 4-stage
// cp.async pipeline, 3 CTAs/SM.
//   out[i,m] = inv_degree[i] * sum_kk G[i,kk] * W[kk,m]   (fp16 x fp16 -> fp32)
// 8 warps (4m x 2n), warp tile 16x64.
// Smem swizzles:
//   A tile [64][32] fp16  (64B rows, 4 chunks):  chunk' = c ^ ((row>>1)&3)
//   B tile [32][128] fp16 (256B rows, 16 chunks): chunk' = c ^ (row&15)
// ---------------------------------------------------------------------------
#define BM        64
#define KC        32
#define NKCHUNKS  (KDIM / KC)         // 32
#define OFF_A     0
#define OFF_B     4096
#define BUF_BYTES 12288               // 4K (A) + 8K (B)
#define NSTAGES   4
#define SMEM_DYN  (NSTAGES * BUF_BYTES)   // 48 KB

__global__ void __launch_bounds__(256, 3) stage2_mma_kernel(
    const float* __restrict__ inv_degree,
    float* __restrict__ out)
{
    extern __shared__ __align__(128) char smem[];
    const uint32_t sbase = smem_u32(smem);

    const int tid    = threadIdx.x;
    const int lane   = tid & 31;
    const int wid    = tid >> 5;
    const int warp_m = wid & 3;        // m offset 16*warp_m
    const int warp_n = wid >> 2;       // n offset 64*warp_n
    const int m0     = blockIdx.x * BM;

    float acc[8][4];
#pragma unroll
    for (int nt = 0; nt < 8; nt++)
#pragma unroll
        for (int q = 0; q < 4; q++) acc[nt][q] = 0.f;

    // ---- async load of one K-chunk into stage buffer b; always commits ----
    auto load_chunk = [&](int kc, int b) {
        if (kc < NKCHUNKS) {
            const uint32_t sb = sbase + b * BUF_BYTES;
            // A: 64 rows x 32 cols fp16 = 256 x 16B chunks (1 per thread)
            {
                const int row = tid >> 2;
                const int c   = tid & 3;
                const uint32_t so = row * 64 + ((c ^ ((row >> 1) & 3)) << 4);
                const size_t ge = (size_t)(m0 + row) * KDIM + kc * KC + c * 8;
                cp_async16(sb + OFF_A + so, g_h + ge);
            }
            // B: 32 rows x 128 cols fp16 = 512 x 16B chunks (2 per thread)
#pragma unroll
            for (int it = 0; it < 2; it++) {
                const int cb  = tid + it * 256;
                const int row = cb >> 4;
                const int c   = cb & 15;
                const uint32_t so = row * 256 + ((c ^ (row & 15)) << 4);
                const size_t ge = (size_t)(kc * KC + row) * FDIM + c * 8;
                cp_async16(sb + OFF_B + so, wt_h + ge);
            }
        }
        cp_commit();
    };

    load_chunk(0, 0);
    load_chunk(1, 1);
    load_chunk(2, 2);

#pragma unroll 1
    for (int kc = 0; kc < NKCHUNKS; kc++) {
        asm volatile("cp.async.wait_group 2;");
        __syncthreads();

        load_chunk(kc + 3, (kc + 3) % NSTAGES);

        const uint32_t sb = sbase + (kc % NSTAGES) * BUF_BYTES;

#pragma unroll
        for (int k16 = 0; k16 < 2; k16++) {
            uint32_t af[4];
            const int rA   = (lane & 7) + ((lane >> 3) & 1) * 8;
            const int kch  = k16 * 2 + (lane >> 4);
            {
                const int row = warp_m * 16 + rA;
                const uint32_t off = row * 64 + ((kch ^ ((row >> 1) & 3)) << 4);
                ldm_x4(af, sb + OFF_A + off);
            }
            const int rB = k16 * 16 + (lane & 7) + ((lane >> 3) & 1) * 8;
#pragma unroll
            for (int nt16 = 0; nt16 < 4; nt16++) {
                const int nch = warp_n * 8 + nt16 * 2 + (lane >> 4);
                const uint32_t off = rB * 256 + ((nch ^ (rB & 15)) << 4);
                uint32_t bf[4];
                ldm_x4t(bf, sb + OFF_B + off);
                mma_f16(acc[nt16 * 2 + 0], af, bf + 0);
                mma_f16(acc[nt16 * 2 + 1], af, bf + 2);
            }
        }
    }

    // ---- epilogue: scale + store ----
    {
        const int r0 = m0 + warp_m * 16 + (lane >> 2);
        const int r1 = r0 + 8;
        const float s0 = (r0 < N_NODES) ? inv_degree[r0] : 0.f;
        const float s1 = (r1 < N_NODES) ? inv_degree[r1] : 0.f;
#pragma unroll
        for (int nt = 0; nt < 8; nt++) {
            const int col = warp_n * 64 + nt * 8 + (lane & 3) * 2;
            if (r0 < N_NODES) {
                float2 o = make_float2(acc[nt][0] * s0, acc[nt][1] * s0);
                *(float2*)(out + (size_t)r0 * FDIM + col) = o;
            }
            if (r1 < N_NODES) {
                float2 o = make_float2(acc[nt][2] * s1, acc[nt][3] * s1);
                *(float2*)(out + (size_t)r1 * FDIM + col) = o;
            }
        }
    }
}

// ---------------------------------------------------------------------------
// Launch. Inputs identified BY ELEMENT COUNT (all five distinct).
// ---------------------------------------------------------------------------
extern "C" void kernel_launch(void* const* d_in, const int* in_sizes, int n_in,
                              void* d_out, int out_size) {
    const float* nodes      = nullptr;
    const int*   nlist      = nullptr;
    const float* edges      = nullptr;
    const float* inv_degree = nullptr;
    const float* w          = nullptr;

    for (int i = 0; i < n_in; i++) {
        switch (in_sizes[i]) {
            case 6400000:  nodes      = (const float*)d_in[i]; break;
            case 1600000:  nlist      = (const int*)d_in[i];   break;
            case 12800000: edges      = (const float*)d_in[i]; break;
            case 50000:    inv_degree = (const float*)d_in[i]; break;
            case 131072:   w          = (const float*)d_in[i]; break;
            default: break;
        }
    }
    if (!nodes || !nlist || !edges || !inv_degree || !w) return;

    float* out = (float*)d_out;

    cudaFuncSetAttribute(stage2_mma_kernel,
                         cudaFuncAttributeMaxDynamicSharedMemorySize, SMEM_DYN);

    transpose_w_kernel<<<(KDIM * FDIM + 255) / 256, 256>>>(w);
    convert_nodes_kernel<<<(N_NODES * FDIM / 4 + 255) / 256, 256>>>(nodes);
    stage1_kernel<<<N_NODES / 8, 256>>>(nlist, edges);
    stage2_mma_kernel<<<(N_NODES + BM - 1) / BM, 256, SMEM_DYN>>>(inv_degree, out);
}

// round 12
// speedup vs baseline: 1.1121x; 1.1121x over previous
#include <cuda_runtime.h>
#include <cuda_fp16.h>
#include <cstdint>
#include <cstddef>

// Problem constants
#define N_NODES 50000
#define N_PAD   50048
#define KNBR    32
#define FDIM    128
#define EDIM    8
#define KDIM    1024          // FDIM * EDIM

// G as fp16, rows [i][kk], kk = n*128 + l
// (__device__ globals zero-init; padded rows [50000,50048) stay zero.)
__device__ __half g_h[(size_t)N_PAD * KDIM];   // 102.5 MB
// W rearranged to [kk][m] fp16
__device__ __half wt_h[KDIM * FDIM];

// ---------------------------------------------------------------------------
// helpers
// ---------------------------------------------------------------------------
__device__ __forceinline__ uint32_t smem_u32(const void* p) {
    uint32_t a;
    asm("{ .reg .u64 t; cvta.to.shared.u64 t, %1; cvt.u32.u64 %0, t; }" : "=r"(a) : "l"(p));
    return a;
}

__device__ __forceinline__ void cp_async16(uint32_t dst, const void* src) {
    asm volatile("cp.async.cg.shared.global [%0], [%1], 16;" :: "r"(dst), "l"(src));
}
__device__ __forceinline__ void cp_commit() {
    asm volatile("cp.async.commit_group;");
}

__device__ __forceinline__ void ldm_x4(uint32_t* r, uint32_t addr) {
    asm volatile("ldmatrix.sync.aligned.m8n8.x4.shared.b16 {%0,%1,%2,%3}, [%4];"
                 : "=r"(r[0]), "=r"(r[1]), "=r"(r[2]), "=r"(r[3]) : "r"(addr));
}
__device__ __forceinline__ void ldm_x4t(uint32_t* r, uint32_t addr) {
    asm volatile("ldmatrix.sync.aligned.m8n8.x4.trans.shared.b16 {%0,%1,%2,%3}, [%4];"
                 : "=r"(r[0]), "=r"(r[1]), "=r"(r[2]), "=r"(r[3]) : "r"(addr));
}

__device__ __forceinline__ void mma_f16(float* c, const uint32_t* a, const uint32_t* b) {
    asm volatile(
        "mma.sync.aligned.m16n8k16.row.col.f32.f16.f16.f32 "
        "{%0,%1,%2,%3}, {%4,%5,%6,%7}, {%8,%9}, {%0,%1,%2,%3};"
        : "+f"(c[0]), "+f"(c[1]), "+f"(c[2]), "+f"(c[3])
        : "r"(a[0]), "r"(a[1]), "r"(a[2]), "r"(a[3]), "r"(b[0]), "r"(b[1]));
}

__device__ __forceinline__ void fma4(float4& a, float s, const float4& x) {
    a.x = fmaf(s, x.x, a.x);
    a.y = fmaf(s, x.y, a.y);
    a.z = fmaf(s, x.z, a.z);
    a.w = fmaf(s, x.w, a.w);
}

// ---------------------------------------------------------------------------
// Kernel 0: w (F,F,E) -> wt_h [kk][m],  kk = n*128 + l
// ---------------------------------------------------------------------------
__global__ void transpose_w_kernel(const float* __restrict__ w) {
    int idx = blockIdx.x * blockDim.x + threadIdx.x;
    if (idx >= KDIM * FDIM) return;
    int kk = idx >> 7;          // n*128 + l
    int m  = idx & 127;
    int n  = kk >> 7;
    int l  = kk & 127;
    wt_h[idx] = __float2half_rn(w[(l * FDIM + m) * EDIM + n]);
}

// ---------------------------------------------------------------------------
// Kernel 1: stage 1 — G row, fp32 gather + fp32 accumulate, store fp16
// One warp per node i. Lane owns l = lane*4..lane*4+3.
// nlist is int32 (proven on hardware).
// ---------------------------------------------------------------------------
__global__ void __launch_bounds__(256) stage1_kernel(
    const float* __restrict__ nodes,
    const int* __restrict__ nlist,
    const float* __restrict__ edges)
{
    __shared__ int   s_nb[8][KNBR];
    __shared__ float s_e[8][KNBR * EDIM];

    const int warp = threadIdx.x >> 5;
    const int lane = threadIdx.x & 31;
    const int i = blockIdx.x * 8 + warp;

    int nbi = nlist[(size_t)i * KNBR + lane];
    nbi = nbi < 0 ? 0 : (nbi >= N_NODES ? N_NODES - 1 : nbi);   // safety clamp
    s_nb[warp][lane] = nbi;

    const float4* e4 = (const float4*)(edges + (size_t)i * (KNBR * EDIM));
    float4* se4 = (float4*)s_e[warp];
    se4[lane * 2 + 0] = e4[lane * 2 + 0];
    se4[lane * 2 + 1] = e4[lane * 2 + 1];
    __syncwarp();

    float4 acc[EDIM];
#pragma unroll
    for (int n = 0; n < EDIM; n++) acc[n] = make_float4(0.f, 0.f, 0.f, 0.f);

#pragma unroll 4
    for (int j = 0; j < KNBR; j++) {
        const int nb = s_nb[warp][j];
        const float4 x = *(const float4*)(nodes + (size_t)nb * FDIM + lane * 4);
        const float4 e0 = *(const float4*)&s_e[warp][j * 8 + 0];
        const float4 e1 = *(const float4*)&s_e[warp][j * 8 + 4];
        fma4(acc[0], e0.x, x);
        fma4(acc[1], e0.y, x);
        fma4(acc[2], e0.z, x);
        fma4(acc[3], e0.w, x);
        fma4(acc[4], e1.x, x);
        fma4(acc[5], e1.y, x);
        fma4(acc[6], e1.z, x);
        fma4(acc[7], e1.w, x);
    }

    const size_t rbase = (size_t)i * KDIM + lane * 4;
#pragma unroll
    for (int n = 0; n < EDIM; n++) {
        __half2 a = __floats2half2_rn(acc[n].x, acc[n].y);
        __half2 b = __floats2half2_rn(acc[n].z, acc[n].w);
        *(uint2*)&g_h[rbase + n * FDIM] = make_uint2(*(uint32_t*)&a, *(uint32_t*)&b);
    }
}

// ---------------------------------------------------------------------------
// Kernel 2: mma.sync fp16 single-product GEMM, BM=64 x BN=128, 4-stage
// cp.async pipeline, 3 CTAs/SM.
//   out[i,m] = inv_degree[i] * sum_kk G[i,kk] * W[kk,m]   (fp16 x fp16 -> fp32)
// 8 warps (4m x 2n), warp tile 16x64.
// TILE ORDER REVERSED: stage1 writes G rows ascending, so the highest rows
// are the L2-resident ones when stage2 starts; consuming them first converts
// a large fraction of the 102.5 MB G read from DRAM to L2 hits.
// Smem swizzles:
//   A tile [64][32] fp16  (64B rows, 4 chunks):  chunk' = c ^ ((row>>1)&3)
//   B tile [32][128] fp16 (256B rows, 16 chunks): chunk' = c ^ (row&15)
// ---------------------------------------------------------------------------
#define BM        64
#define KC        32
#define NKCHUNKS  (KDIM / KC)         // 32
#define OFF_A     0
#define OFF_B     4096
#define BUF_BYTES 12288               // 4K (A) + 8K (B)
#define NSTAGES   4
#define SMEM_DYN  (NSTAGES * BUF_BYTES)   // 48 KB
#define NBLOCKS_M ((N_NODES + BM - 1) / BM)   // 782

__global__ void __launch_bounds__(256, 3) stage2_mma_kernel(
    const float* __restrict__ inv_degree,
    float* __restrict__ out)
{
    extern __shared__ __align__(128) char smem[];
    const uint32_t sbase = smem_u32(smem);

    const int tid    = threadIdx.x;
    const int lane   = tid & 31;
    const int wid    = tid >> 5;
    const int warp_m = wid & 3;        // m offset 16*warp_m
    const int warp_n = wid >> 2;       // n offset 64*warp_n
    // reversed tile order: hottest (last-written) G rows first
    const int m0     = (NBLOCKS_M - 1 - blockIdx.x) * BM;

    float acc[8][4];
#pragma unroll
    for (int nt = 0; nt < 8; nt++)
#pragma unroll
        for (int q = 0; q < 4; q++) acc[nt][q] = 0.f;

    // ---- async load of one K-chunk into stage buffer b; always commits ----
    auto load_chunk = [&](int kc, int b) {
        if (kc < NKCHUNKS) {
            const uint32_t sb = sbase + b * BUF_BYTES;
            // A: 64 rows x 32 cols fp16 = 256 x 16B chunks (1 per thread)
            {
                const int row = tid >> 2;
                const int c   = tid & 3;
                const uint32_t so = row * 64 + ((c ^ ((row >> 1) & 3)) << 4);
                const size_t ge = (size_t)(m0 + row) * KDIM + kc * KC + c * 8;
                cp_async16(sb + OFF_A + so, g_h + ge);
            }
            // B: 32 rows x 128 cols fp16 = 512 x 16B chunks (2 per thread)
#pragma unroll
            for (int it = 0; it < 2; it++) {
                const int cb  = tid + it * 256;
                const int row = cb >> 4;
                const int c   = cb & 15;
                const uint32_t so = row * 256 + ((c ^ (row & 15)) << 4);
                const size_t ge = (size_t)(kc * KC + row) * FDIM + c * 8;
                cp_async16(sb + OFF_B + so, wt_h + ge);
            }
        }
        cp_commit();
    };

    load_chunk(0, 0);
    load_chunk(1, 1);
    load_chunk(2, 2);

#pragma unroll 1
    for (int kc = 0; kc < NKCHUNKS; kc++) {
        asm volatile("cp.async.wait_group 2;");
        __syncthreads();

        load_chunk(kc + 3, (kc + 3) % NSTAGES);

        const uint32_t sb = sbase + (kc % NSTAGES) * BUF_BYTES;

#pragma unroll
        for (int k16 = 0; k16 < 2; k16++) {
            uint32_t af[4];
            const int rA   = (lane & 7) + ((lane >> 3) & 1) * 8;
            const int kch  = k16 * 2 + (lane >> 4);
            {
                const int row = warp_m * 16 + rA;
                const uint32_t off = row * 64 + ((kch ^ ((row >> 1) & 3)) << 4);
                ldm_x4(af, sb + OFF_A + off);
            }
            const int rB = k16 * 16 + (lane & 7) + ((lane >> 3) & 1) * 8;
#pragma unroll
            for (int nt16 = 0; nt16 < 4; nt16++) {
                const int nch = warp_n * 8 + nt16 * 2 + (lane >> 4);
                const uint32_t off = rB * 256 + ((nch ^ (rB & 15)) << 4);
                uint32_t bf[4];
                ldm_x4t(bf, sb + OFF_B + off);
                mma_f16(acc[nt16 * 2 + 0], af, bf + 0);
                mma_f16(acc[nt16 * 2 + 1], af, bf + 2);
            }
        }
    }

    // ---- epilogue: scale + store ----
    {
        const int r0 = m0 + warp_m * 16 + (lane >> 2);
        const int r1 = r0 + 8;
        const float s0 = (r0 < N_NODES) ? inv_degree[r0] : 0.f;
        const float s1 = (r1 < N_NODES) ? inv_degree[r1] : 0.f;
#pragma unroll
        for (int nt = 0; nt < 8; nt++) {
            const int col = warp_n * 64 + nt * 8 + (lane & 3) * 2;
            if (r0 < N_NODES) {
                float2 o = make_float2(acc[nt][0] * s0, acc[nt][1] * s0);
                *(float2*)(out + (size_t)r0 * FDIM + col) = o;
            }
            if (r1 < N_NODES) {
                float2 o = make_float2(acc[nt][2] * s1, acc[nt][3] * s1);
                *(float2*)(out + (size_t)r1 * FDIM + col) = o;
            }
        }
    }
}

// ---------------------------------------------------------------------------
// Launch. Inputs identified BY ELEMENT COUNT (all five distinct).
// ---------------------------------------------------------------------------
extern "C" void kernel_launch(void* const* d_in, const int* in_sizes, int n_in,
                              void* d_out, int out_size) {
    const float* nodes      = nullptr;
    const int*   nlist      = nullptr;
    const float* edges      = nullptr;
    const float* inv_degree = nullptr;
    const float* w          = nullptr;

    for (int i = 0; i < n_in; i++) {
        switch (in_sizes[i]) {
            case 6400000:  nodes      = (const float*)d_in[i]; break;
            case 1600000:  nlist      = (const int*)d_in[i];   break;
            case 12800000: edges      = (const float*)d_in[i]; break;
            case 50000:    inv_degree = (const float*)d_in[i]; break;
            case 131072:   w          = (const float*)d_in[i]; break;
            default: break;
        }
    }
    if (!nodes || !nlist || !edges || !inv_degree || !w) return;

    float* out = (float*)d_out;

    cudaFuncSetAttribute(stage2_mma_kernel,
                         cudaFuncAttributeMaxDynamicSharedMemorySize, SMEM_DYN);

    transpose_w_kernel<<<(KDIM * FDIM + 255) / 256, 256>>>(w);
    stage1_kernel<<<N_NODES / 8, 256>>>(nodes, nlist, edges);
    stage2_mma_kernel<<<NBLOCKS_M, 256, SMEM_DYN>>>(inv_degree, out);
}